// round 10
// baseline (speedup 1.0000x reference)
#include <cuda_runtime.h>
#include <cuda_bf16.h>
#include <cstdint>

#define IN_F   4096
#define OUT_F  4096
#define LORA_R 64
#define M_TOTAL 8192

// ---------------- device scratch ----------------
__device__ int8_t g_q1[(size_t)M_TOTAL * IN_F];     // 33.5 MB
__device__ int8_t g_q2[(size_t)M_TOTAL * IN_F];     // 33.5 MB
__device__ int8_t g_w8[(size_t)OUT_F * IN_F];       // 16.8 MB
__device__ float  g_beta[M_TOTAL];                  // s * alpha_m
__device__ __nv_bfloat16 g_t[(size_t)M_TOTAL * LORA_R];
__device__ int g_wq_is_i32;

__device__ __forceinline__ uint32_t smem_u32(const void* p) {
    uint32_t a;
    asm("{ .reg .u64 t; cvta.to.shared.u64 t, %1; cvt.u32.u64 %0, t; }" : "=r"(a) : "l"(p));
    return a;
}

// ---------------- kernel 0: dtype detect ----------------
__global__ void detect_wq_dtype_kernel(const int* __restrict__ wq) {
    __shared__ int bad;
    if (threadIdx.x == 0) bad = 0;
    __syncthreads();
    int v = wq[threadIdx.x * 257];
    if (v < -8 || v > 7) bad = 1;
    __syncthreads();
    if (threadIdx.x == 0) g_wq_is_i32 = !bad;
}

// ---------------- kernel 1: per-row double quantization of x ----------------
// x[m][k] ~= alpha_m * (q1 + q2/254), q1,q2 int8. beta_m = s * alpha_m.
__global__ __launch_bounds__(128) void quant_x_kernel(
    const float* __restrict__ x, const float* __restrict__ ws)
{
    const int m = blockIdx.x;
    const int tid = threadIdx.x;
    const float* row = x + (size_t)m * IN_F;

    float4 v[8];
    float mx = 0.f;
#pragma unroll
    for (int u = 0; u < 8; ++u) {
        v[u] = reinterpret_cast<const float4*>(row)[u * 128 + tid];
        mx = fmaxf(mx, fmaxf(fmaxf(fabsf(v[u].x), fabsf(v[u].y)),
                             fmaxf(fabsf(v[u].z), fabsf(v[u].w))));
    }
#pragma unroll
    for (int o = 16; o > 0; o >>= 1)
        mx = fmaxf(mx, __shfl_xor_sync(0xFFFFFFFF, mx, o));
    __shared__ float wmax[4];
    if ((tid & 31) == 0) wmax[tid >> 5] = mx;
    __syncthreads();
    float rmax = fmaxf(fmaxf(wmax[0], wmax[1]), fmaxf(wmax[2], wmax[3]));
    float alpha = fmaxf(rmax / 127.f, 1e-20f);
    float ia = 1.f / alpha;
    if (tid == 0) g_beta[m] = ws[0] * alpha;

    char4* q1p = reinterpret_cast<char4*>(g_q1 + (size_t)m * IN_F);
    char4* q2p = reinterpret_cast<char4*>(g_q2 + (size_t)m * IN_F);
#pragma unroll
    for (int u = 0; u < 8; ++u) {
        float f[4] = {v[u].x, v[u].y, v[u].z, v[u].w};
        char q1c[4], q2c[4];
#pragma unroll
        for (int j = 0; j < 4; ++j) {
            float q1 = rintf(f[j] * ia);
            float r  = f[j] - alpha * q1;
            float q2 = rintf(r * ia * 254.f);
            q1c[j] = (char)(int)q1;
            q2c[j] = (char)(int)q2;
        }
        q1p[u * 128 + tid] = make_char4(q1c[0], q1c[1], q1c[2], q1c[3]);
        q2p[u * 128 + tid] = make_char4(q2c[0], q2c[1], q2c[2], q2c[3]);
    }
}

// ---------------- kernel 2: Wq -> int8 ----------------
__global__ __launch_bounds__(256) void conv_w_kernel(const void* __restrict__ wqv) {
    size_t i = ((size_t)blockIdx.x * 256 + threadIdx.x) * 4;
    if (g_wq_is_i32) {
        int4 q = *reinterpret_cast<const int4*>((const int*)wqv + i);
        *reinterpret_cast<char4*>(g_w8 + i) =
            make_char4((char)q.x, (char)q.y, (char)q.z, (char)q.w);
    } else {
        *reinterpret_cast<char4*>(g_w8 + i) =
            *reinterpret_cast<const char4*>((const int8_t*)wqv + i);
    }
}

// ---------------- kernel 3: t = 0.25 * x @ A^T (bf16 out) ----------------
__global__ __launch_bounds__(256) void t_kernel(
    const float* __restrict__ x, const float* __restrict__ A)
{
    __shared__ float xs[64][33];
    __shared__ float as[64][33];
    const int tid = threadIdx.x;
    const int bm = blockIdx.x;
    const int tr = tid >> 4, tc = tid & 15;

    float acc[4][4];
#pragma unroll
    for (int i = 0; i < 4; ++i)
#pragma unroll
        for (int j = 0; j < 4; ++j) acc[i][j] = 0.f;

    for (int k0 = 0; k0 < IN_F; k0 += 32) {
#pragma unroll
        for (int u = 0; u < 2; ++u) {
            int idx = tid + u * 256;
            int row = idx >> 3, c = idx & 7;
            float4 xv = *reinterpret_cast<const float4*>(
                x + (size_t)(bm * 64 + row) * IN_F + k0 + c * 4);
            float4 av = *reinterpret_cast<const float4*>(
                A + (size_t)row * IN_F + k0 + c * 4);
            xs[row][c * 4 + 0] = xv.x; xs[row][c * 4 + 1] = xv.y;
            xs[row][c * 4 + 2] = xv.z; xs[row][c * 4 + 3] = xv.w;
            as[row][c * 4 + 0] = av.x; as[row][c * 4 + 1] = av.y;
            as[row][c * 4 + 2] = av.z; as[row][c * 4 + 3] = av.w;
        }
        __syncthreads();
#pragma unroll
        for (int kk = 0; kk < 32; ++kk) {
            float xv[4], av[4];
#pragma unroll
            for (int i = 0; i < 4; ++i) xv[i] = xs[tr * 4 + i][kk];
#pragma unroll
            for (int j = 0; j < 4; ++j) av[j] = as[tc * 4 + j][kk];
#pragma unroll
            for (int i = 0; i < 4; ++i)
#pragma unroll
                for (int j = 0; j < 4; ++j)
                    acc[i][j] = fmaf(xv[i], av[j], acc[i][j]);
        }
        __syncthreads();
    }
#pragma unroll
    for (int i = 0; i < 4; ++i)
#pragma unroll
        for (int j = 0; j < 4; ++j)
            g_t[(size_t)(bm * 64 + tr * 4 + i) * LORA_R + tc * 4 + j] =
                __float2bfloat16(0.25f * acc[i][j]);
}

// ---------------- shared mma helpers ----------------
__device__ __forceinline__ void ldmx4(uint32_t addr, uint32_t& r0, uint32_t& r1,
                                      uint32_t& r2, uint32_t& r3) {
    asm volatile("ldmatrix.sync.aligned.m8n8.x4.shared.b16 {%0,%1,%2,%3}, [%4];"
                 : "=r"(r0), "=r"(r1), "=r"(r2), "=r"(r3) : "r"(addr));
}
__device__ __forceinline__ void mma16816(float* c, const uint32_t* a, const uint32_t* b) {
    asm volatile(
        "mma.sync.aligned.m16n8k16.row.col.f32.bf16.bf16.f32 "
        "{%0,%1,%2,%3}, {%4,%5,%6,%7}, {%8,%9}, {%0,%1,%2,%3};"
        : "+f"(c[0]), "+f"(c[1]), "+f"(c[2]), "+f"(c[3])
        : "r"(a[0]), "r"(a[1]), "r"(a[2]), "r"(a[3]), "r"(b[0]), "r"(b[1]));
}
__device__ __forceinline__ void imma16832(int* c, const uint32_t* a, const uint32_t* b) {
    asm volatile(
        "mma.sync.aligned.m16n8k32.row.col.s32.s8.s8.s32 "
        "{%0,%1,%2,%3}, {%4,%5,%6,%7}, {%8,%9}, {%0,%1,%2,%3};"
        : "+r"(c[0]), "+r"(c[1]), "+r"(c[2]), "+r"(c[3])
        : "r"(a[0]), "r"(a[1]), "r"(a[2]), "r"(a[3]), "r"(b[0]), "r"(b[1]));
}
__device__ __forceinline__ void cp16(uint32_t dst, const void* src) {
    asm volatile("cp.async.cg.shared.global [%0], [%1], 16;" :: "r"(dst), "l"(src) : "memory");
}

// ---------------- kernel 4: lora write-out (out = t @ B^T) ----------------
// CTA 128(M) x 128(N), 8 warps (2m x 4n), warp 64x32, K=64 bf16.
#define LSTR 72
__global__ __launch_bounds__(256) void lora_kernel(
    const float* __restrict__ B, float* __restrict__ out)
{
    __shared__ __align__(16) __nv_bfloat16 sT[128 * LSTR];
    __shared__ __align__(16) __nv_bfloat16 sB[128 * LSTR];
    const int tid = threadIdx.x, wid = tid >> 5, lane = tid & 31;
    const int warp_m = wid & 1, warp_n = wid >> 1;
    const int bm = blockIdx.y, bn = blockIdx.x;

    // stage t (bf16) and B (f32 -> bf16): 1024 16B-chunks each, 4/thread
#pragma unroll
    for (int u = 0; u < 4; ++u) {
        int c = tid + u * 256;
        int row = c >> 3, cc = c & 7;
        *reinterpret_cast<uint4*>(&sT[row * LSTR + cc * 8]) =
            *reinterpret_cast<const uint4*>(g_t + (size_t)(bm * 128 + row) * LORA_R + cc * 8);
        const float* bp = B + (size_t)(bn * 128 + row) * LORA_R + cc * 8;
        float4 f0 = reinterpret_cast<const float4*>(bp)[0];
        float4 f1 = reinterpret_cast<const float4*>(bp)[1];
        __nv_bfloat162* d = reinterpret_cast<__nv_bfloat162*>(&sB[row * LSTR + cc * 8]);
        d[0] = __nv_bfloat162(__float2bfloat16(f0.x), __float2bfloat16(f0.y));
        d[1] = __nv_bfloat162(__float2bfloat16(f0.z), __float2bfloat16(f0.w));
        d[2] = __nv_bfloat162(__float2bfloat16(f1.x), __float2bfloat16(f1.y));
        d[3] = __nv_bfloat162(__float2bfloat16(f1.z), __float2bfloat16(f1.w));
    }
    __syncthreads();

    float acc[4][4][4];
#pragma unroll
    for (int i = 0; i < 4; ++i)
#pragma unroll
        for (int j = 0; j < 4; ++j)
#pragma unroll
            for (int r = 0; r < 4; ++r) acc[i][j][r] = 0.f;

    const uint32_t bT = smem_u32(sT), bW = smem_u32(sB);
    const int rowA = warp_m * 64 + (lane & 15);
    const int rowW = warp_n * 32 + (lane & 15);
    const int koff = (lane >> 4) * 8;
#pragma unroll
    for (int ks = 0; ks < 4; ++ks) {
        const int kb = ks * 16 + koff;
        uint32_t af[4][4], bf[4][2];
#pragma unroll
        for (int mf = 0; mf < 4; ++mf)
            ldmx4(bT + (uint32_t)((rowA + mf * 16) * LSTR + kb) * 2,
                  af[mf][0], af[mf][1], af[mf][2], af[mf][3]);
#pragma unroll
        for (int nf2 = 0; nf2 < 2; ++nf2) {
            uint32_t r0, r1, r2, r3;
            ldmx4(bW + (uint32_t)((rowW + nf2 * 16) * LSTR + kb) * 2, r0, r1, r2, r3);
            bf[nf2 * 2 + 0][0] = r0; bf[nf2 * 2 + 0][1] = r2;
            bf[nf2 * 2 + 1][0] = r1; bf[nf2 * 2 + 1][1] = r3;
        }
#pragma unroll
        for (int mf = 0; mf < 4; ++mf)
#pragma unroll
            for (int nf = 0; nf < 4; ++nf)
                mma16816(acc[mf][nf], af[mf], bf[nf]);
    }

    const int g = lane >> 2, t4 = lane & 3;
#pragma unroll
    for (int mf = 0; mf < 4; ++mf)
#pragma unroll
        for (int nf = 0; nf < 4; ++nf) {
            int m = bm * 128 + warp_m * 64 + mf * 16 + g;
            int n = bn * 128 + warp_n * 32 + nf * 8 + t4 * 2;
            *reinterpret_cast<float2*>(out + (size_t)m * OUT_F + n) =
                make_float2(acc[mf][nf][0], acc[mf][nf][1]);
            *reinterpret_cast<float2*>(out + (size_t)(m + 8) * OUT_F + n) =
                make_float2(acc[mf][nf][2], acc[mf][nf][3]);
        }
}

// ---------------- kernel 5: main int8 IMMA GEMM ----------------
// out += beta_m * (q1@W + q2@W/254).  CTA 128x128, 8 warps (2m x 4n),
// warp 64x32, BK=64 int8, two persistent s32 accumulator sets, 4-stage ring.
#define SSTR8 80
#define NT8 (IN_F / 64)
#define STG (3 * 128 * SSTR8)
#define STAGES 4
#define SMEM_MAIN (STAGES * STG)

__global__ __launch_bounds__(256, 1) void qlora_imma_kernel(float* __restrict__ out)
{
    extern __shared__ __align__(16) int8_t smem[];
    __shared__ float sBeta[128];

    const int tid = threadIdx.x, wid = tid >> 5, lane = tid & 31;
    const int warp_m = wid & 1, warp_n = wid >> 1;
    const int bm = blockIdx.y, bn = blockIdx.x;
    const uint32_t sbase = smem_u32(smem);

    if (tid < 128) sBeta[tid] = g_beta[bm * 128 + tid];

    int acc1[4][4][4], acc2[4][4][4];
#pragma unroll
    for (int i = 0; i < 4; ++i)
#pragma unroll
        for (int j = 0; j < 4; ++j)
#pragma unroll
            for (int r = 0; r < 4; ++r) { acc1[i][j][r] = 0; acc2[i][j][r] = 0; }

    auto issue = [&](int kt) {
        if (kt < NT8) {
            const int s = kt & (STAGES - 1);
            const uint32_t d1 = sbase + s * STG;
            const uint32_t d2 = d1 + 128 * SSTR8;
            const uint32_t dW = d2 + 128 * SSTR8;
            const int ko = kt * 64;
#pragma unroll
            for (int u = 0; u < 2; ++u) {
                int c = tid + u * 256;
                int row = c >> 2, kc = (c & 3) * 16;
                size_t offA = (size_t)(bm * 128 + row) * IN_F + ko + kc;
                size_t offW = (size_t)(bn * 128 + row) * IN_F + ko + kc;
                cp16(d1 + row * SSTR8 + kc, g_q1 + offA);
                cp16(d2 + row * SSTR8 + kc, g_q2 + offA);
                cp16(dW + row * SSTR8 + kc, g_w8 + offW);
            }
        }
        asm volatile("cp.async.commit_group;" ::: "memory");
    };

    issue(0); issue(1); issue(2);

    const int rowA = warp_m * 64 + (lane & 15);
    const int rowW = warp_n * 32 + (lane & 15);
    const int kboff = (lane >> 4) * 16;

    for (int kt = 0; kt < NT8; ++kt) {
        const int s = kt & (STAGES - 1);
        asm volatile("cp.async.wait_group 2;" ::: "memory");
        __syncthreads();
        issue(kt + 3);

        const uint32_t b1 = sbase + s * STG;
        const uint32_t b2 = b1 + 128 * SSTR8;
        const uint32_t bW = b2 + 128 * SSTR8;
#pragma unroll
        for (int ks = 0; ks < 2; ++ks) {
            const int kb = ks * 32 + kboff;
            uint32_t af1[4][4], af2[4][4], bf[4][2];
#pragma unroll
            for (int mf = 0; mf < 4; ++mf) {
                ldmx4(b1 + (uint32_t)((rowA + mf * 16) * SSTR8 + kb),
                      af1[mf][0], af1[mf][1], af1[mf][2], af1[mf][3]);
                ldmx4(b2 + (uint32_t)((rowA + mf * 16) * SSTR8 + kb),
                      af2[mf][0], af2[mf][1], af2[mf][2], af2[mf][3]);
            }
#pragma unroll
            for (int nf2 = 0; nf2 < 2; ++nf2) {
                uint32_t r0, r1, r2, r3;
                ldmx4(bW + (uint32_t)((rowW + nf2 * 16) * SSTR8 + kb), r0, r1, r2, r3);
                bf[nf2 * 2 + 0][0] = r0; bf[nf2 * 2 + 0][1] = r2;
                bf[nf2 * 2 + 1][0] = r1; bf[nf2 * 2 + 1][1] = r3;
            }
#pragma unroll
            for (int mf = 0; mf < 4; ++mf)
#pragma unroll
                for (int nf = 0; nf < 4; ++nf) {
                    imma16832(acc1[mf][nf], af1[mf], bf[nf]);
                    imma16832(acc2[mf][nf], af2[mf], bf[nf]);
                }
        }
    }

    const float inv254 = 1.f / 254.f;
    const int g = lane >> 2, t4 = lane & 3;
#pragma unroll
    for (int mf = 0; mf < 4; ++mf)
#pragma unroll
        for (int nf = 0; nf < 4; ++nf) {
            int ml = warp_m * 64 + mf * 16 + g;
            int m = bm * 128 + ml;
            int n = bn * 128 + warp_n * 32 + nf * 8 + t4 * 2;
            float bt0 = sBeta[ml], bt1 = sBeta[ml + 8];
            float2* p0 = reinterpret_cast<float2*>(out + (size_t)m * OUT_F + n);
            float2* p1 = reinterpret_cast<float2*>(out + (size_t)(m + 8) * OUT_F + n);
            float2 o0 = *p0, o1 = *p1;
            o0.x += bt0 * ((float)acc1[mf][nf][0] + inv254 * (float)acc2[mf][nf][0]);
            o0.y += bt0 * ((float)acc1[mf][nf][1] + inv254 * (float)acc2[mf][nf][1]);
            o1.x += bt1 * ((float)acc1[mf][nf][2] + inv254 * (float)acc2[mf][nf][2]);
            o1.y += bt1 * ((float)acc1[mf][nf][3] + inv254 * (float)acc2[mf][nf][3]);
            *p0 = o0; *p1 = o1;
        }
}

// ---------------- launch ----------------
extern "C" void kernel_launch(void* const* d_in, const int* in_sizes, int n_in,
                              void* d_out, int out_size)
{
    const float* x  = nullptr;
    const void*  wq = nullptr;
    const float* ws = nullptr;
    const float* la = nullptr;
    const float* lb = nullptr;

    int lora_seen = 0;
    for (int i = 0; i < n_in; ++i) {
        long n = (long)in_sizes[i];
        if (n == 33554432L)      x  = (const float*)d_in[i];
        else if (n == 16777216L) wq = d_in[i];
        else if (n == 1L)        ws = (const float*)d_in[i];
        else if (n == 262144L) {
            if (lora_seen++ == 0) la = (const float*)d_in[i];
            else                  lb = (const float*)d_in[i];
        }
    }
    float* out = (float*)d_out;

    cudaFuncSetAttribute(qlora_imma_kernel,
                         cudaFuncAttributeMaxDynamicSharedMemorySize, SMEM_MAIN);

    // order matters: main kernel is the 6th launch -> captured by ncu -s 5 -c 1
    detect_wq_dtype_kernel<<<1, 256>>>((const int*)wq);
    quant_x_kernel<<<M_TOTAL, 128>>>(x, ws);
    conv_w_kernel<<<(OUT_F * IN_F / 4) / 256, 256>>>(wq);
    t_kernel<<<M_TOTAL / 64, 256>>>(x, la);
    lora_kernel<<<dim3(OUT_F / 128, M_TOTAL / 128), 256>>>(lb, out);
    qlora_imma_kernel<<<dim3(OUT_F / 128, M_TOTAL / 128), 256, SMEM_MAIN>>>(out);
}

// round 11
// speedup vs baseline: 3.2168x; 3.2168x over previous
#include <cuda_runtime.h>
#include <cuda_fp16.h>
#include <cstdint>

#define IN_F   4096
#define OUT_F  4096
#define LORA_R 64
#define M_TOTAL 8192

// ---------------- device scratch ----------------
__device__ __half g_xf[(size_t)M_TOTAL * IN_F];    // fp16(s*x)  64 MB
__device__ __half g_wf[(size_t)OUT_F * IN_F];      // fp16(Wq)   32 MB (exact)
__device__ __half g_bf[(size_t)OUT_F * LORA_R];    // fp16(lora_B)
__device__ __half g_t[(size_t)M_TOTAL * LORA_R];   // fp16(0.25 * x @ A^T)
__device__ int g_wq_is_i32;

__device__ __forceinline__ uint32_t smem_u32(const void* p) {
    uint32_t a;
    asm("{ .reg .u64 t; cvta.to.shared.u64 t, %1; cvt.u32.u64 %0, t; }" : "=r"(a) : "l"(p));
    return a;
}

// ---------------- kernel 0: dtype detect ----------------
__global__ void detect_wq_dtype_kernel(const int* __restrict__ wq) {
    __shared__ int bad;
    if (threadIdx.x == 0) bad = 0;
    __syncthreads();
    int v = wq[threadIdx.x * 257];
    if (v < -8 || v > 7) bad = 1;
    __syncthreads();
    if (threadIdx.x == 0) g_wq_is_i32 = !bad;
}

// ---------------- kernel 1: x -> fp16(s*x) ----------------
__global__ __launch_bounds__(256) void conv_x_kernel(
    const float* __restrict__ x, const float* __restrict__ ws)
{
    const float s = ws[0];
    size_t i = (size_t)blockIdx.x * 256 + threadIdx.x;   // float4 index
    float4 v = reinterpret_cast<const float4*>(x)[i];
    __half2* p = reinterpret_cast<__half2*>(g_xf) + i * 2;
    p[0] = __floats2half2_rn(s * v.x, s * v.y);
    p[1] = __floats2half2_rn(s * v.z, s * v.w);
}

// ---------------- kernel 2: Wq -> fp16 (exact for [-8,7]) ----------------
__global__ __launch_bounds__(256) void conv_w_kernel(const void* __restrict__ wqv) {
    size_t i = ((size_t)blockIdx.x * 256 + threadIdx.x) * 4;
    __half2* p = reinterpret_cast<__half2*>(g_wf + i);
    if (g_wq_is_i32) {
        int4 q = *reinterpret_cast<const int4*>((const int*)wqv + i);
        p[0] = __floats2half2_rn((float)q.x, (float)q.y);
        p[1] = __floats2half2_rn((float)q.z, (float)q.w);
    } else {
        const int8_t* c = (const int8_t*)wqv + i;
        p[0] = __floats2half2_rn((float)c[0], (float)c[1]);
        p[1] = __floats2half2_rn((float)c[2], (float)c[3]);
    }
}

// ---------------- kernel 3: lora_B -> fp16 ----------------
__global__ __launch_bounds__(256) void conv_b_kernel(const float* __restrict__ B) {
    size_t i = ((size_t)blockIdx.x * 256 + threadIdx.x) * 4;
    float4 v = *reinterpret_cast<const float4*>(B + i);
    __half2* p = reinterpret_cast<__half2*>(g_bf + i);
    p[0] = __floats2half2_rn(v.x, v.y);
    p[1] = __floats2half2_rn(v.z, v.w);
}

// ---------------- kernel 4: t = 0.25 * x @ A^T -> fp16 ----------------
// grid 256 blocks (32 m-rows each), 256 threads, thread tile 2m x 4r.
__global__ __launch_bounds__(256) void t_kernel(
    const float* __restrict__ x, const float* __restrict__ A)
{
    __shared__ float xs[32][33];
    __shared__ float as[64][33];
    const int tid = threadIdx.x;
    const int bm = blockIdx.x;
    const int tr = tid >> 4, tc = tid & 15;

    float acc[2][4];
#pragma unroll
    for (int i = 0; i < 2; ++i)
#pragma unroll
        for (int j = 0; j < 4; ++j) acc[i][j] = 0.f;

    for (int k0 = 0; k0 < IN_F; k0 += 32) {
        {   // x: 32 rows x 8 float4 = 256 chunks -> 1/thread
            int row = tid >> 3, c = tid & 7;
            float4 xv = *reinterpret_cast<const float4*>(
                x + (size_t)(bm * 32 + row) * IN_F + k0 + c * 4);
            xs[row][c * 4 + 0] = xv.x; xs[row][c * 4 + 1] = xv.y;
            xs[row][c * 4 + 2] = xv.z; xs[row][c * 4 + 3] = xv.w;
        }
#pragma unroll
        for (int u = 0; u < 2; ++u) {   // A: 64 rows x 8 float4 = 512 -> 2/thread
            int idx = tid + u * 256;
            int row = idx >> 3, c = idx & 7;
            float4 av = *reinterpret_cast<const float4*>(
                A + (size_t)row * IN_F + k0 + c * 4);
            as[row][c * 4 + 0] = av.x; as[row][c * 4 + 1] = av.y;
            as[row][c * 4 + 2] = av.z; as[row][c * 4 + 3] = av.w;
        }
        __syncthreads();
#pragma unroll
        for (int kk = 0; kk < 32; ++kk) {
            float xv[2], av[4];
#pragma unroll
            for (int i = 0; i < 2; ++i) xv[i] = xs[tr * 2 + i][kk];
#pragma unroll
            for (int j = 0; j < 4; ++j) av[j] = as[tc * 4 + j][kk];
#pragma unroll
            for (int i = 0; i < 2; ++i)
#pragma unroll
                for (int j = 0; j < 4; ++j)
                    acc[i][j] = fmaf(xv[i], av[j], acc[i][j]);
        }
        __syncthreads();
    }
#pragma unroll
    for (int i = 0; i < 2; ++i)
#pragma unroll
        for (int j = 0; j < 4; ++j)
            g_t[(size_t)(bm * 32 + tr * 2 + i) * LORA_R + tc * 4 + j] =
                __float2half_rn(0.25f * acc[i][j]);
}

// ---------------- kernel 5: main fp16 mma GEMM ----------------
// out[m][n] = xf@wf (K=4096) + t@bf (K=64), K-concatenated -> 130 tiles.
// CTA 256(M) x 128(N), BK=32, 8 warps (4m x 2n), warp tile 64x64, 4-stage ring.
#define SSTR 40
#define NTILES (IN_F / 32 + 2)          // 130
#define A_ROWS 256
#define W_ROWS 128
#define STAGE_H ((A_ROWS + W_ROWS) * SSTR)   // 15360 halves
#define STAGES 4
#define SMEM_MAIN (STAGES * STAGE_H * 2)      // 122880 B

__device__ __forceinline__ void cp16(uint32_t dst, const void* src) {
    asm volatile("cp.async.cg.shared.global [%0], [%1], 16;" :: "r"(dst), "l"(src) : "memory");
}
__device__ __forceinline__ void ldmx4(uint32_t addr, uint32_t& r0, uint32_t& r1,
                                      uint32_t& r2, uint32_t& r3) {
    asm volatile("ldmatrix.sync.aligned.m8n8.x4.shared.b16 {%0,%1,%2,%3}, [%4];"
                 : "=r"(r0), "=r"(r1), "=r"(r2), "=r"(r3) : "r"(addr));
}
__device__ __forceinline__ void mma16816(float* c, const uint32_t* a, const uint32_t* b) {
    asm volatile(
        "mma.sync.aligned.m16n8k16.row.col.f32.f16.f16.f32 "
        "{%0,%1,%2,%3}, {%4,%5,%6,%7}, {%8,%9}, {%0,%1,%2,%3};"
        : "+f"(c[0]), "+f"(c[1]), "+f"(c[2]), "+f"(c[3])
        : "r"(a[0]), "r"(a[1]), "r"(a[2]), "r"(a[3]), "r"(b[0]), "r"(b[1]));
}

__global__ __launch_bounds__(256, 1) void qlora_mma_kernel(float* __restrict__ out)
{
    extern __shared__ __align__(16) __half smem[];

    const int tid  = threadIdx.x;
    const int wid  = tid >> 5;
    const int lane = tid & 31;
    const int warp_m = wid & 3;
    const int warp_n = wid >> 2;
    const int bm = blockIdx.y, bn = blockIdx.x;
    const uint32_t sbase = smem_u32(smem);

    float acc[4][8][4];
#pragma unroll
    for (int i = 0; i < 4; ++i)
#pragma unroll
        for (int j = 0; j < 8; ++j)
#pragma unroll
            for (int r = 0; r < 4; ++r) acc[i][j][r] = 0.f;

    auto issue = [&](int kt) {
        if (kt < NTILES) {
            const int s = kt & (STAGES - 1);
            const __half *aSrc, *wSrc;
            int lda, ko;
            if (kt < IN_F / 32) { aSrc = g_xf; wSrc = g_wf; lda = IN_F;   ko = kt * 32; }
            else                { aSrc = g_t;  wSrc = g_bf; lda = LORA_R; ko = (kt - IN_F / 32) * 32; }
            const __half* aBase = aSrc + (size_t)(bm * A_ROWS) * lda + ko;
            const __half* wBase = wSrc + (size_t)(bn * W_ROWS) * lda + ko;
            const uint32_t dA = sbase + (uint32_t)(s * STAGE_H) * 2;
            const uint32_t dW = dA + (uint32_t)(A_ROWS * SSTR) * 2;
#pragma unroll
            for (int u = 0; u < 4; ++u) {          // A: 1024 chunks
                int c = tid + u * 256;
                int row = c >> 2, kc = (c & 3) * 8;
                cp16(dA + (uint32_t)(row * SSTR + kc) * 2, aBase + (size_t)row * lda + kc);
            }
#pragma unroll
            for (int u = 0; u < 2; ++u) {          // W: 512 chunks
                int c = tid + u * 256;
                int row = c >> 2, kc = (c & 3) * 8;
                cp16(dW + (uint32_t)(row * SSTR + kc) * 2, wBase + (size_t)row * lda + kc);
            }
        }
        asm volatile("cp.async.commit_group;" ::: "memory");
    };

    issue(0); issue(1); issue(2);

    const int rowA = warp_m * 64 + (lane & 15);
    const int rowW = warp_n * 64 + (lane & 7) + ((lane >> 3) & 1) * 8;
    const int koff = (lane >> 4) * 8;

    for (int kt = 0; kt < NTILES; ++kt) {
        const int s = kt & (STAGES - 1);
        asm volatile("cp.async.wait_group 2;" ::: "memory");
        __syncthreads();
        issue(kt + 3);

        const uint32_t bA = sbase + (uint32_t)(s * STAGE_H) * 2;
        const uint32_t bW = bA + (uint32_t)(A_ROWS * SSTR) * 2;
#pragma unroll
        for (int ks = 0; ks < 2; ++ks) {
            const int kb = ks * 16 + koff;
            uint32_t af[4][4], bf[8][2];
#pragma unroll
            for (int mf = 0; mf < 4; ++mf)
                ldmx4(bA + (uint32_t)((rowA + mf * 16) * SSTR + kb) * 2,
                      af[mf][0], af[mf][1], af[mf][2], af[mf][3]);
#pragma unroll
            for (int nf2 = 0; nf2 < 4; ++nf2) {
                uint32_t r0, r1, r2, r3;
                ldmx4(bW + (uint32_t)((rowW + nf2 * 16) * SSTR + kb) * 2, r0, r1, r2, r3);
                bf[nf2 * 2 + 0][0] = r0; bf[nf2 * 2 + 0][1] = r2;
                bf[nf2 * 2 + 1][0] = r1; bf[nf2 * 2 + 1][1] = r3;
            }
#pragma unroll
            for (int mf = 0; mf < 4; ++mf)
#pragma unroll
                for (int nf = 0; nf < 8; ++nf)
                    mma16816(acc[mf][nf], af[mf], bf[nf]);
        }
    }

    const int g = lane >> 2, t4 = lane & 3;
#pragma unroll
    for (int mf = 0; mf < 4; ++mf) {
#pragma unroll
        for (int nf = 0; nf < 8; ++nf) {
            int m = bm * 256 + warp_m * 64 + mf * 16 + g;
            int n = bn * 128 + warp_n * 64 + nf * 8 + t4 * 2;
            *reinterpret_cast<float2*>(out + (size_t)m * OUT_F + n) =
                make_float2(acc[mf][nf][0], acc[mf][nf][1]);
            *reinterpret_cast<float2*>(out + (size_t)(m + 8) * OUT_F + n) =
                make_float2(acc[mf][nf][2], acc[mf][nf][3]);
        }
    }
}

// ---------------- launch ----------------
extern "C" void kernel_launch(void* const* d_in, const int* in_sizes, int n_in,
                              void* d_out, int out_size)
{
    const float* x  = nullptr;
    const void*  wq = nullptr;
    const float* ws = nullptr;
    const float* la = nullptr;
    const float* lb = nullptr;

    int lora_seen = 0;
    for (int i = 0; i < n_in; ++i) {
        long n = (long)in_sizes[i];
        if (n == 33554432L)      x  = (const float*)d_in[i];
        else if (n == 16777216L) wq = d_in[i];
        else if (n == 1L)        ws = (const float*)d_in[i];
        else if (n == 262144L) {
            if (lora_seen++ == 0) la = (const float*)d_in[i];
            else                  lb = (const float*)d_in[i];
        }
    }
    float* out = (float*)d_out;

    cudaFuncSetAttribute(qlora_mma_kernel,
                         cudaFuncAttributeMaxDynamicSharedMemorySize, SMEM_MAIN);

    // main kernel is the 6th launch -> captured by ncu -s 5 -c 1
    detect_wq_dtype_kernel<<<1, 256>>>((const int*)wq);
    conv_x_kernel<<<(M_TOTAL * IN_F / 4) / 256, 256>>>(x, ws);
    conv_w_kernel<<<(OUT_F * IN_F / 4) / 256, 256>>>(wq);
    conv_b_kernel<<<(OUT_F * LORA_R / 4) / 256, 256>>>(lb);
    t_kernel<<<M_TOTAL / 32, 256>>>(x, la);
    qlora_mma_kernel<<<dim3(OUT_F / 128, M_TOTAL / 256), 256, SMEM_MAIN>>>(out);
}

// round 12
// speedup vs baseline: 4.1516x; 1.2906x over previous
#include <cuda_runtime.h>
#include <cuda_fp16.h>
#include <cstdint>

#define IN_F   4096
#define OUT_F  4096
#define LORA_R 64
#define M_TOTAL 8192

// ---------------- device scratch ----------------
__device__ __half g_xf[(size_t)M_TOTAL * IN_F];    // fp16(s*x)  64 MB
__device__ __half g_wf[(size_t)OUT_F * IN_F];      // fp16(Wq)   32 MB (exact)
__device__ __half g_af[(size_t)LORA_R * IN_F];     // fp16(lora_A)
__device__ __half g_bf[(size_t)OUT_F * LORA_R];    // fp16(lora_B)
__device__ __half g_t[(size_t)M_TOTAL * LORA_R];   // fp16(0.25 * x @ A^T)

__device__ __forceinline__ uint32_t smem_u32(const void* p) {
    uint32_t a;
    asm("{ .reg .u64 t; cvta.to.shared.u64 t, %1; cvt.u32.u64 %0, t; }" : "=r"(a) : "l"(p));
    return a;
}

// ---------------- kernel 1: x -> fp16(s*x) ----------------
__global__ __launch_bounds__(256) void conv_x_kernel(
    const float* __restrict__ x, const float* __restrict__ ws)
{
    const float s = ws[0];
    size_t i = (size_t)blockIdx.x * 256 + threadIdx.x;   // float4 index
    float4 v = reinterpret_cast<const float4*>(x)[i];
    __half2* p = reinterpret_cast<__half2*>(g_xf) + i * 2;
    p[0] = __floats2half2_rn(s * v.x, s * v.y);
    p[1] = __floats2half2_rn(s * v.z, s * v.w);
}

// ---------------- kernel 2: lora_A and lora_B -> fp16 (fused) ----------------
__global__ __launch_bounds__(256) void conv_ab_kernel(
    const float* __restrict__ A, const float* __restrict__ B)
{
    size_t i = ((size_t)blockIdx.x * 256 + threadIdx.x) * 4;
    const size_t NA = (size_t)LORA_R * IN_F;
    if (i < NA) {
        float4 v = *reinterpret_cast<const float4*>(A + i);
        __half2* p = reinterpret_cast<__half2*>(g_af + i);
        p[0] = __floats2half2_rn(v.x, v.y);
        p[1] = __floats2half2_rn(v.z, v.w);
    } else {
        size_t j = i - NA;
        float4 v = *reinterpret_cast<const float4*>(B + j);
        __half2* p = reinterpret_cast<__half2*>(g_bf + j);
        p[0] = __floats2half2_rn(v.x, v.y);
        p[1] = __floats2half2_rn(v.z, v.w);
    }
}

// ---------------- kernel 3: Wq -> fp16, with per-block dtype detect ----------------
// If all 1024 int32 words this block would process lie in [-8,7], the buffer is
// int32-widened int8; a packed-int8 buffer read as int32 passes with prob ~0.
__global__ __launch_bounds__(256) void conv_w_kernel(const void* __restrict__ wqv) {
    __shared__ int s_is_i32;
    size_t i = ((size_t)blockIdx.x * 256 + threadIdx.x) * 4;
    int4 q = *reinterpret_cast<const int4*>((const int*)wqv + i);
    bool ok = (q.x >= -8 && q.x <= 7) && (q.y >= -8 && q.y <= 7) &&
              (q.z >= -8 && q.z <= 7) && (q.w >= -8 && q.w <= 7);
    if (threadIdx.x == 0) s_is_i32 = 1;
    __syncthreads();
    if (!ok) s_is_i32 = 0;
    __syncthreads();
    __half2* p = reinterpret_cast<__half2*>(g_wf + i);
    if (s_is_i32) {
        p[0] = __floats2half2_rn((float)q.x, (float)q.y);
        p[1] = __floats2half2_rn((float)q.z, (float)q.w);
    } else {
        const int8_t* c = (const int8_t*)wqv + i;
        p[0] = __floats2half2_rn((float)c[0], (float)c[1]);
        p[1] = __floats2half2_rn((float)c[2], (float)c[3]);
    }
}

// ---------------- shared mma helpers ----------------
__device__ __forceinline__ void cp16(uint32_t dst, const void* src) {
    asm volatile("cp.async.cg.shared.global [%0], [%1], 16;" :: "r"(dst), "l"(src) : "memory");
}
__device__ __forceinline__ void ldmx4(uint32_t addr, uint32_t& r0, uint32_t& r1,
                                      uint32_t& r2, uint32_t& r3) {
    asm volatile("ldmatrix.sync.aligned.m8n8.x4.shared.b16 {%0,%1,%2,%3}, [%4];"
                 : "=r"(r0), "=r"(r1), "=r"(r2), "=r"(r3) : "r"(addr));
}
__device__ __forceinline__ void mma16816(float* c, const uint32_t* a, const uint32_t* b) {
    asm volatile(
        "mma.sync.aligned.m16n8k16.row.col.f32.f16.f16.f32 "
        "{%0,%1,%2,%3}, {%4,%5,%6,%7}, {%8,%9}, {%0,%1,%2,%3};"
        : "+f"(c[0]), "+f"(c[1]), "+f"(c[2]), "+f"(c[3])
        : "r"(a[0]), "r"(a[1]), "r"(a[2]), "r"(a[3]), "r"(b[0]), "r"(b[1]));
}

// ---------------- kernel 4: t = (0.25/s) * xf @ af^T  (fp16 mma) ----------------
// CTA 128(M) x 64(N=LORA_R), BK=32, 2-stage, 8 warps (4m x 2n), warp 32x32.
#define TSTR 40
__global__ __launch_bounds__(256) void t_mma_kernel(const float* __restrict__ ws)
{
    __shared__ __align__(16) __half sm[2][(128 + 64) * TSTR];
    const int tid = threadIdx.x, wid = tid >> 5, lane = tid & 31;
    const int warp_m = wid & 3, warp_n = wid >> 2;
    const int bm = blockIdx.x;

    float acc[2][4][4];
#pragma unroll
    for (int i = 0; i < 2; ++i)
#pragma unroll
        for (int j = 0; j < 4; ++j)
#pragma unroll
            for (int r = 0; r < 4; ++r) acc[i][j][r] = 0.f;

    auto issue = [&](int kt) {
        if (kt < IN_F / 32) {
            const int s = kt & 1;
            const uint32_t dA = smem_u32(&sm[s][0]);
            const uint32_t dW = dA + (uint32_t)(128 * TSTR) * 2;
            const int ko = kt * 32;
#pragma unroll
            for (int u = 0; u < 2; ++u) {   // A: 512 chunks
                int c = tid + u * 256;
                int row = c >> 2, kc = (c & 3) * 8;
                cp16(dA + (uint32_t)(row * TSTR + kc) * 2,
                     g_xf + (size_t)(bm * 128 + row) * IN_F + ko + kc);
            }
            {   // W: 256 chunks
                int row = tid >> 2, kc = (tid & 3) * 8;
                if (row < 64)
                    cp16(dW + (uint32_t)(row * TSTR + kc) * 2,
                         g_af + (size_t)row * IN_F + ko + kc);
            }
        }
        asm volatile("cp.async.commit_group;" ::: "memory");
    };

    issue(0);
    const int rowA = warp_m * 32 + (lane & 15);
    const int rowW = warp_n * 32 + (lane & 7) + ((lane >> 3) & 1) * 8;
    const int koff = (lane >> 4) * 8;

    for (int kt = 0; kt < IN_F / 32; ++kt) {
        const int s = kt & 1;
        issue(kt + 1);
        asm volatile("cp.async.wait_group 1;" ::: "memory");
        __syncthreads();

        const uint32_t bA = smem_u32(&sm[s][0]);
        const uint32_t bW = bA + (uint32_t)(128 * TSTR) * 2;
#pragma unroll
        for (int ks = 0; ks < 2; ++ks) {
            const int kb = ks * 16 + koff;
            uint32_t af[2][4], bf[4][2];
#pragma unroll
            for (int mf = 0; mf < 2; ++mf)
                ldmx4(bA + (uint32_t)((rowA + mf * 16) * TSTR + kb) * 2,
                      af[mf][0], af[mf][1], af[mf][2], af[mf][3]);
#pragma unroll
            for (int nf2 = 0; nf2 < 2; ++nf2) {
                uint32_t r0, r1, r2, r3;
                ldmx4(bW + (uint32_t)((rowW + nf2 * 16) * TSTR + kb) * 2, r0, r1, r2, r3);
                bf[nf2 * 2 + 0][0] = r0; bf[nf2 * 2 + 0][1] = r2;
                bf[nf2 * 2 + 1][0] = r1; bf[nf2 * 2 + 1][1] = r3;
            }
#pragma unroll
            for (int mf = 0; mf < 2; ++mf)
#pragma unroll
                for (int nf = 0; nf < 4; ++nf)
                    mma16816(acc[mf][nf], af[mf], bf[nf]);
        }
        __syncthreads();
    }

    const float sc = 0.25f / ws[0];
    const int g = lane >> 2, t4 = lane & 3;
#pragma unroll
    for (int mf = 0; mf < 2; ++mf)
#pragma unroll
        for (int nf = 0; nf < 4; ++nf) {
            int m = bm * 128 + warp_m * 32 + mf * 16 + g;
            int n = warp_n * 32 + nf * 8 + t4 * 2;
            *reinterpret_cast<__half2*>(g_t + (size_t)m * LORA_R + n) =
                __floats2half2_rn(sc * acc[mf][nf][0], sc * acc[mf][nf][1]);
            *reinterpret_cast<__half2*>(g_t + (size_t)(m + 8) * LORA_R + n) =
                __floats2half2_rn(sc * acc[mf][nf][2], sc * acc[mf][nf][3]);
        }
}

// ---------------- kernel 5: main fp16 mma GEMM ----------------
// out = xf@wf (K=4096) + t@bf (K=64). CTA 256x128, BK=64, 3-stage ring,
// 8 warps (4m x 2n), warp tile 64x64.
#define SSTR 72
#define NTILES (IN_F / 64 + 1)           // 65
#define A_ROWS 256
#define W_ROWS 128
#define STAGE_H ((A_ROWS + W_ROWS) * SSTR)    // 27648 halves = 55296 B
#define STAGES 3
#define SMEM_MAIN (STAGES * STAGE_H * 2)       // 165888 B

__global__ __launch_bounds__(256, 1) void qlora_mma_kernel(float* __restrict__ out)
{
    extern __shared__ __align__(16) __half smem[];

    const int tid  = threadIdx.x;
    const int wid  = tid >> 5;
    const int lane = tid & 31;
    const int warp_m = wid & 3;
    const int warp_n = wid >> 2;
    const int bm = blockIdx.y, bn = blockIdx.x;
    const uint32_t sbase = smem_u32(smem);

    float acc[4][8][4];
#pragma unroll
    for (int i = 0; i < 4; ++i)
#pragma unroll
        for (int j = 0; j < 8; ++j)
#pragma unroll
            for (int r = 0; r < 4; ++r) acc[i][j][r] = 0.f;

    auto issue = [&](int kt) {
        if (kt < NTILES) {
            const int s = kt % STAGES;
            const __half *aSrc, *wSrc;
            int lda, ko;
            if (kt < IN_F / 64) { aSrc = g_xf; wSrc = g_wf; lda = IN_F;   ko = kt * 64; }
            else                { aSrc = g_t;  wSrc = g_bf; lda = LORA_R; ko = 0; }
            const __half* aBase = aSrc + (size_t)(bm * A_ROWS) * lda + ko;
            const __half* wBase = wSrc + (size_t)(bn * W_ROWS) * lda + ko;
            const uint32_t dA = sbase + (uint32_t)(s * STAGE_H) * 2;
            const uint32_t dW = dA + (uint32_t)(A_ROWS * SSTR) * 2;
#pragma unroll
            for (int u = 0; u < 8; ++u) {          // A: 2048 16B-chunks
                int c = tid + u * 256;
                int row = c >> 3, kc = (c & 7) * 8;
                cp16(dA + (uint32_t)(row * SSTR + kc) * 2, aBase + (size_t)row * lda + kc);
            }
#pragma unroll
            for (int u = 0; u < 4; ++u) {          // W: 1024 chunks
                int c = tid + u * 256;
                int row = c >> 3, kc = (c & 7) * 8;
                cp16(dW + (uint32_t)(row * SSTR + kc) * 2, wBase + (size_t)row * lda + kc);
            }
        }
        asm volatile("cp.async.commit_group;" ::: "memory");
    };

    issue(0); issue(1);

    const int rowA = warp_m * 64 + (lane & 15);
    const int rowW = warp_n * 64 + (lane & 7) + ((lane >> 3) & 1) * 8;
    const int koff = (lane >> 4) * 8;

    for (int kt = 0; kt < NTILES; ++kt) {
        const int s = kt % STAGES;
        asm volatile("cp.async.wait_group 1;" ::: "memory");
        __syncthreads();
        issue(kt + 2);

        const uint32_t bA = sbase + (uint32_t)(s * STAGE_H) * 2;
        const uint32_t bW = bA + (uint32_t)(A_ROWS * SSTR) * 2;
#pragma unroll
        for (int ks = 0; ks < 4; ++ks) {
            const int kb = ks * 16 + koff;
            uint32_t af[4][4], bf[8][2];
#pragma unroll
            for (int mf = 0; mf < 4; ++mf)
                ldmx4(bA + (uint32_t)((rowA + mf * 16) * SSTR + kb) * 2,
                      af[mf][0], af[mf][1], af[mf][2], af[mf][3]);
#pragma unroll
            for (int nf2 = 0; nf2 < 4; ++nf2) {
                uint32_t r0, r1, r2, r3;
                ldmx4(bW + (uint32_t)((rowW + nf2 * 16) * SSTR + kb) * 2, r0, r1, r2, r3);
                bf[nf2 * 2 + 0][0] = r0; bf[nf2 * 2 + 0][1] = r2;
                bf[nf2 * 2 + 1][0] = r1; bf[nf2 * 2 + 1][1] = r3;
            }
#pragma unroll
            for (int mf = 0; mf < 4; ++mf)
#pragma unroll
                for (int nf = 0; nf < 8; ++nf)
                    mma16816(acc[mf][nf], af[mf], bf[nf]);
        }
    }

    const int g = lane >> 2, t4 = lane & 3;
#pragma unroll
    for (int mf = 0; mf < 4; ++mf) {
#pragma unroll
        for (int nf = 0; nf < 8; ++nf) {
            int m = bm * 256 + warp_m * 64 + mf * 16 + g;
            int n = bn * 128 + warp_n * 64 + nf * 8 + t4 * 2;
            *reinterpret_cast<float2*>(out + (size_t)m * OUT_F + n) =
                make_float2(acc[mf][nf][0], acc[mf][nf][1]);
            *reinterpret_cast<float2*>(out + (size_t)(m + 8) * OUT_F + n) =
                make_float2(acc[mf][nf][2], acc[mf][nf][3]);
        }
    }
}

// ---------------- launch ----------------
extern "C" void kernel_launch(void* const* d_in, const int* in_sizes, int n_in,
                              void* d_out, int out_size)
{
    const float* x  = nullptr;
    const void*  wq = nullptr;
    const float* ws = nullptr;
    const float* la = nullptr;
    const float* lb = nullptr;

    int lora_seen = 0;
    for (int i = 0; i < n_in; ++i) {
        long n = (long)in_sizes[i];
        if (n == 33554432L)      x  = (const float*)d_in[i];
        else if (n == 16777216L) wq = d_in[i];
        else if (n == 1L)        ws = (const float*)d_in[i];
        else if (n == 262144L) {
            if (lora_seen++ == 0) la = (const float*)d_in[i];
            else                  lb = (const float*)d_in[i];
        }
    }
    float* out = (float*)d_out;

    cudaFuncSetAttribute(qlora_mma_kernel,
                         cudaFuncAttributeMaxDynamicSharedMemorySize, SMEM_MAIN);

    conv_x_kernel<<<(M_TOTAL * IN_F / 4) / 256, 256>>>(x, ws);
    conv_ab_kernel<<<2 * (LORA_R * IN_F / 4) / 256, 256>>>(la, lb);
    conv_w_kernel<<<(OUT_F * IN_F / 4) / 256, 256>>>(wq);
    t_mma_kernel<<<M_TOTAL / 128, 256>>>(ws);
    qlora_mma_kernel<<<dim3(OUT_F / 128, M_TOTAL / 256), 256, SMEM_MAIN>>>(out);
}

// round 13
// speedup vs baseline: 4.1763x; 1.0060x over previous
#include <cuda_runtime.h>
#include <cuda_fp16.h>
#include <cstdint>

#define IN_F   4096
#define OUT_F  4096
#define LORA_R 64
#define M_TOTAL 8192

// ---------------- device scratch ----------------
__device__ __half g_xf[(size_t)M_TOTAL * IN_F];    // fp16(s*x)  64 MB
__device__ __half g_wf[(size_t)OUT_F * IN_F];      // fp16(Wq)   32 MB (exact)
__device__ __half g_af[(size_t)LORA_R * IN_F];     // fp16(lora_A)
__device__ __half g_bf[(size_t)OUT_F * LORA_R];    // fp16(lora_B)
__device__ __half g_t[(size_t)M_TOTAL * LORA_R];   // fp16(0.25 * x @ A^T)

__device__ __forceinline__ uint32_t smem_u32(const void* p) {
    uint32_t a;
    asm("{ .reg .u64 t; cvta.to.shared.u64 t, %1; cvt.u32.u64 %0, t; }" : "=r"(a) : "l"(p));
    return a;
}

// ---------------- kernel 1: fused conversions ----------------
// blocks [0, XB):        x -> fp16(s*x)
// blocks [XB, XB+WB):    Wq -> fp16 (per-block int32/int8 detect)
// blocks [XB+WB, ...):   lora_A, lora_B -> fp16
#define XB (M_TOTAL * IN_F / 4 / 256)        // 32768
#define WB (OUT_F * IN_F / 4 / 256)          // 16384
#define ABB (2 * LORA_R * IN_F / 4 / 256)    // 512

__global__ __launch_bounds__(256) void conv_all_kernel(
    const float* __restrict__ x, const void* __restrict__ wqv,
    const float* __restrict__ A, const float* __restrict__ B,
    const float* __restrict__ ws)
{
    const int b = blockIdx.x;
    if (b < XB) {
        const float s = ws[0];
        size_t i = (size_t)b * 256 + threadIdx.x;
        float4 v = reinterpret_cast<const float4*>(x)[i];
        __half2* p = reinterpret_cast<__half2*>(g_xf) + i * 2;
        p[0] = __floats2half2_rn(s * v.x, s * v.y);
        p[1] = __floats2half2_rn(s * v.z, s * v.w);
    } else if (b < XB + WB) {
        __shared__ int s_is_i32;
        size_t i = ((size_t)(b - XB) * 256 + threadIdx.x) * 4;
        int4 q = *reinterpret_cast<const int4*>((const int*)wqv + i);
        bool ok = (q.x >= -8 && q.x <= 7) && (q.y >= -8 && q.y <= 7) &&
                  (q.z >= -8 && q.z <= 7) && (q.w >= -8 && q.w <= 7);
        if (threadIdx.x == 0) s_is_i32 = 1;
        __syncthreads();
        if (!ok) s_is_i32 = 0;
        __syncthreads();
        __half2* p = reinterpret_cast<__half2*>(g_wf + i);
        if (s_is_i32) {
            p[0] = __floats2half2_rn((float)q.x, (float)q.y);
            p[1] = __floats2half2_rn((float)q.z, (float)q.w);
        } else {
            const int8_t* c = (const int8_t*)wqv + i;
            p[0] = __floats2half2_rn((float)c[0], (float)c[1]);
            p[1] = __floats2half2_rn((float)c[2], (float)c[3]);
        }
    } else {
        size_t i = ((size_t)(b - XB - WB) * 256 + threadIdx.x) * 4;
        const size_t NA = (size_t)LORA_R * IN_F;
        if (i < NA) {
            float4 v = *reinterpret_cast<const float4*>(A + i);
            __half2* p = reinterpret_cast<__half2*>(g_af + i);
            p[0] = __floats2half2_rn(v.x, v.y);
            p[1] = __floats2half2_rn(v.z, v.w);
        } else {
            size_t j = i - NA;
            float4 v = *reinterpret_cast<const float4*>(B + j);
            __half2* p = reinterpret_cast<__half2*>(g_bf + j);
            p[0] = __floats2half2_rn(v.x, v.y);
            p[1] = __floats2half2_rn(v.z, v.w);
        }
    }
}

// ---------------- shared mma helpers ----------------
__device__ __forceinline__ void cp16(uint32_t dst, const void* src) {
    asm volatile("cp.async.cg.shared.global [%0], [%1], 16;" :: "r"(dst), "l"(src) : "memory");
}
__device__ __forceinline__ void ldmx4(uint32_t addr, uint32_t& r0, uint32_t& r1,
                                      uint32_t& r2, uint32_t& r3) {
    asm volatile("ldmatrix.sync.aligned.m8n8.x4.shared.b16 {%0,%1,%2,%3}, [%4];"
                 : "=r"(r0), "=r"(r1), "=r"(r2), "=r"(r3) : "r"(addr));
}
__device__ __forceinline__ void mma16816(float* c, const uint32_t* a, const uint32_t* b) {
    asm volatile(
        "mma.sync.aligned.m16n8k16.row.col.f32.f16.f16.f32 "
        "{%0,%1,%2,%3}, {%4,%5,%6,%7}, {%8,%9}, {%0,%1,%2,%3};"
        : "+f"(c[0]), "+f"(c[1]), "+f"(c[2]), "+f"(c[3])
        : "r"(a[0]), "r"(a[1]), "r"(a[2]), "r"(a[3]), "r"(b[0]), "r"(b[1]));
}

// ---------------- kernel 2: t = (0.25/s) * xf @ af^T ----------------
// CTA 64(M) x 64(N), 128 threads, 4 warps (2m x 2n), warp 32x32, BK=32,
// 2-stage. grid = 128 -> fills the chip.
#define TSTR 40
__global__ __launch_bounds__(128) void t_mma_kernel(const float* __restrict__ ws)
{
    __shared__ __align__(16) __half sm[2][(64 + 64) * TSTR];
    const int tid = threadIdx.x, wid = tid >> 5, lane = tid & 31;
    const int warp_m = wid & 1, warp_n = wid >> 1;
    const int bm = blockIdx.x;

    float acc[2][4][4];
#pragma unroll
    for (int i = 0; i < 2; ++i)
#pragma unroll
        for (int j = 0; j < 4; ++j)
#pragma unroll
            for (int r = 0; r < 4; ++r) acc[i][j][r] = 0.f;

    auto issue = [&](int kt) {
        if (kt < IN_F / 32) {
            const int s = kt & 1;
            const uint32_t dA = smem_u32(&sm[s][0]);
            const uint32_t dW = dA + (uint32_t)(64 * TSTR) * 2;
            const int ko = kt * 32;
#pragma unroll
            for (int u = 0; u < 2; ++u) {   // A: 64x32 = 256 chunks -> 2/thread
                int c = tid + u * 128;
                int row = c >> 2, kc = (c & 3) * 8;
                cp16(dA + (uint32_t)(row * TSTR + kc) * 2,
                     g_xf + (size_t)(bm * 64 + row) * IN_F + ko + kc);
            }
#pragma unroll
            for (int u = 0; u < 2; ++u) {   // lora_A: 64x32 = 256 chunks
                int c = tid + u * 128;
                int row = c >> 2, kc = (c & 3) * 8;
                cp16(dW + (uint32_t)(row * TSTR + kc) * 2,
                     g_af + (size_t)row * IN_F + ko + kc);
            }
        }
        asm volatile("cp.async.commit_group;" ::: "memory");
    };

    issue(0);
    const int rowA = warp_m * 32 + (lane & 15);
    const int rowW = warp_n * 32 + (lane & 7) + ((lane >> 3) & 1) * 8;
    const int koff = (lane >> 4) * 8;

    for (int kt = 0; kt < IN_F / 32; ++kt) {
        const int s = kt & 1;
        issue(kt + 1);
        asm volatile("cp.async.wait_group 1;" ::: "memory");
        __syncthreads();

        const uint32_t bA = smem_u32(&sm[s][0]);
        const uint32_t bW = bA + (uint32_t)(64 * TSTR) * 2;
#pragma unroll
        for (int ks = 0; ks < 2; ++ks) {
            const int kb = ks * 16 + koff;
            uint32_t af[2][4], bf[4][2];
#pragma unroll
            for (int mf = 0; mf < 2; ++mf)
                ldmx4(bA + (uint32_t)((rowA + mf * 16) * TSTR + kb) * 2,
                      af[mf][0], af[mf][1], af[mf][2], af[mf][3]);
#pragma unroll
            for (int nf2 = 0; nf2 < 2; ++nf2) {
                uint32_t r0, r1, r2, r3;
                ldmx4(bW + (uint32_t)((rowW + nf2 * 16) * TSTR + kb) * 2, r0, r1, r2, r3);
                bf[nf2 * 2 + 0][0] = r0; bf[nf2 * 2 + 0][1] = r2;
                bf[nf2 * 2 + 1][0] = r1; bf[nf2 * 2 + 1][1] = r3;
            }
#pragma unroll
            for (int mf = 0; mf < 2; ++mf)
#pragma unroll
                for (int nf = 0; nf < 4; ++nf)
                    mma16816(acc[mf][nf], af[mf], bf[nf]);
        }
        __syncthreads();
    }

    const float sc = 0.25f / ws[0];
    const int g = lane >> 2, t4 = lane & 3;
#pragma unroll
    for (int mf = 0; mf < 2; ++mf)
#pragma unroll
        for (int nf = 0; nf < 4; ++nf) {
            int m = bm * 64 + warp_m * 32 + mf * 16 + g;
            int n = warp_n * 32 + nf * 8 + t4 * 2;
            *reinterpret_cast<__half2*>(g_t + (size_t)m * LORA_R + n) =
                __floats2half2_rn(sc * acc[mf][nf][0], sc * acc[mf][nf][1]);
            *reinterpret_cast<__half2*>(g_t + (size_t)(m + 8) * LORA_R + n) =
                __floats2half2_rn(sc * acc[mf][nf][2], sc * acc[mf][nf][3]);
        }
}

// ---------------- kernel 3: main fp16 mma GEMM (unchanged, at HMMA ceiling) ----------------
#define SSTR 72
#define NTILES (IN_F / 64 + 1)           // 65
#define A_ROWS 256
#define W_ROWS 128
#define STAGE_H ((A_ROWS + W_ROWS) * SSTR)
#define STAGES 3
#define SMEM_MAIN (STAGES * STAGE_H * 2)  // 165888 B

__global__ __launch_bounds__(256, 1) void qlora_mma_kernel(float* __restrict__ out)
{
    extern __shared__ __align__(16) __half smem[];

    const int tid  = threadIdx.x;
    const int wid  = tid >> 5;
    const int lane = tid & 31;
    const int warp_m = wid & 3;
    const int warp_n = wid >> 2;
    const int bm = blockIdx.y, bn = blockIdx.x;
    const uint32_t sbase = smem_u32(smem);

    float acc[4][8][4];
#pragma unroll
    for (int i = 0; i < 4; ++i)
#pragma unroll
        for (int j = 0; j < 8; ++j)
#pragma unroll
            for (int r = 0; r < 4; ++r) acc[i][j][r] = 0.f;

    auto issue = [&](int kt) {
        if (kt < NTILES) {
            const int s = kt % STAGES;
            const __half *aSrc, *wSrc;
            int lda, ko;
            if (kt < IN_F / 64) { aSrc = g_xf; wSrc = g_wf; lda = IN_F;   ko = kt * 64; }
            else                { aSrc = g_t;  wSrc = g_bf; lda = LORA_R; ko = 0; }
            const __half* aBase = aSrc + (size_t)(bm * A_ROWS) * lda + ko;
            const __half* wBase = wSrc + (size_t)(bn * W_ROWS) * lda + ko;
            const uint32_t dA = sbase + (uint32_t)(s * STAGE_H) * 2;
            const uint32_t dW = dA + (uint32_t)(A_ROWS * SSTR) * 2;
#pragma unroll
            for (int u = 0; u < 8; ++u) {
                int c = tid + u * 256;
                int row = c >> 3, kc = (c & 7) * 8;
                cp16(dA + (uint32_t)(row * SSTR + kc) * 2, aBase + (size_t)row * lda + kc);
            }
#pragma unroll
            for (int u = 0; u < 4; ++u) {
                int c = tid + u * 256;
                int row = c >> 3, kc = (c & 7) * 8;
                cp16(dW + (uint32_t)(row * SSTR + kc) * 2, wBase + (size_t)row * lda + kc);
            }
        }
        asm volatile("cp.async.commit_group;" ::: "memory");
    };

    issue(0); issue(1);

    const int rowA = warp_m * 64 + (lane & 15);
    const int rowW = warp_n * 64 + (lane & 7) + ((lane >> 3) & 1) * 8;
    const int koff = (lane >> 4) * 8;

    for (int kt = 0; kt < NTILES; ++kt) {
        const int s = kt % STAGES;
        asm volatile("cp.async.wait_group 1;" ::: "memory");
        __syncthreads();
        issue(kt + 2);

        const uint32_t bA = sbase + (uint32_t)(s * STAGE_H) * 2;
        const uint32_t bW = bA + (uint32_t)(A_ROWS * SSTR) * 2;
#pragma unroll
        for (int ks = 0; ks < 4; ++ks) {
            const int kb = ks * 16 + koff;
            uint32_t af[4][4], bf[8][2];
#pragma unroll
            for (int mf = 0; mf < 4; ++mf)
                ldmx4(bA + (uint32_t)((rowA + mf * 16) * SSTR + kb) * 2,
                      af[mf][0], af[mf][1], af[mf][2], af[mf][3]);
#pragma unroll
            for (int nf2 = 0; nf2 < 4; ++nf2) {
                uint32_t r0, r1, r2, r3;
                ldmx4(bW + (uint32_t)((rowW + nf2 * 16) * SSTR + kb) * 2, r0, r1, r2, r3);
                bf[nf2 * 2 + 0][0] = r0; bf[nf2 * 2 + 0][1] = r2;
                bf[nf2 * 2 + 1][0] = r1; bf[nf2 * 2 + 1][1] = r3;
            }
#pragma unroll
            for (int mf = 0; mf < 4; ++mf)
#pragma unroll
                for (int nf = 0; nf < 8; ++nf)
                    mma16816(acc[mf][nf], af[mf], bf[nf]);
        }
    }

    const int g = lane >> 2, t4 = lane & 3;
#pragma unroll
    for (int mf = 0; mf < 4; ++mf) {
#pragma unroll
        for (int nf = 0; nf < 8; ++nf) {
            int m = bm * 256 + warp_m * 64 + mf * 16 + g;
            int n = bn * 128 + warp_n * 64 + nf * 8 + t4 * 2;
            *reinterpret_cast<float2*>(out + (size_t)m * OUT_F + n) =
                make_float2(acc[mf][nf][0], acc[mf][nf][1]);
            *reinterpret_cast<float2*>(out + (size_t)(m + 8) * OUT_F + n) =
                make_float2(acc[mf][nf][2], acc[mf][nf][3]);
        }
    }
}

// ---------------- launch ----------------
extern "C" void kernel_launch(void* const* d_in, const int* in_sizes, int n_in,
                              void* d_out, int out_size)
{
    const float* x  = nullptr;
    const void*  wq = nullptr;
    const float* ws = nullptr;
    const float* la = nullptr;
    const float* lb = nullptr;

    int lora_seen = 0;
    for (int i = 0; i < n_in; ++i) {
        long n = (long)in_sizes[i];
        if (n == 33554432L)      x  = (const float*)d_in[i];
        else if (n == 16777216L) wq = d_in[i];
        else if (n == 1L)        ws = (const float*)d_in[i];
        else if (n == 262144L) {
            if (lora_seen++ == 0) la = (const float*)d_in[i];
            else                  lb = (const float*)d_in[i];
        }
    }
    float* out = (float*)d_out;

    cudaFuncSetAttribute(qlora_mma_kernel,
                         cudaFuncAttributeMaxDynamicSharedMemorySize, SMEM_MAIN);

    conv_all_kernel<<<XB + WB + ABB, 256>>>(x, wq, la, lb, ws);
    t_mma_kernel<<<M_TOTAL / 64, 128>>>(ws);
    qlora_mma_kernel<<<dim3(OUT_F / 128, M_TOTAL / 256), 256, SMEM_MAIN>>>(out);
}